// round 1
// baseline (speedup 1.0000x reference)
#include <cuda_runtime.h>

// Problem constants (fixed by setup_inputs)
#define BATCH 128
#define IC    2048
#define OC    32
#define OD    16
#define ROW   512          // OC*OD floats per (b,i) row
#define WARPS_PER_BATCH 64
#define I_PER_WARP      32 // IC / WARPS_PER_BATCH
#define BLOCKS_PER_BATCH 8 // 8 warps per block
#define THREADS 256

// Scratch (device globals: allocation-free per harness rules)
__device__ __align__(16) float g_partial[(size_t)BATCH * WARPS_PER_BATCH * ROW]; // 16 MB
__device__ __align__(16) float g_v[(size_t)BATCH * ROW];                          // 256 KB
__device__ __align__(16) float g_bb[(size_t)BATCH * IC * OC];                     // 32 MB

// One routing step: optionally compute agreement b += u.v, softmax over OC,
// accumulate s partials per warp.
//   AGREE=false : c = softmax(b_in[i,:])                    (init pass)
//   AGREE=true  : logits = bsrc + dot(u, v_prev); c = softmax(logits)
//   BSRC_BATCHED: bsrc = g_bb[b,i,:]  else  bsrc = b_in[i,:]
//   WRITE_B     : store logits back to g_bb (skipped on last iteration)
template<bool AGREE, bool BSRC_BATCHED, bool WRITE_B>
__global__ __launch_bounds__(THREADS)
void rba_compute_s(const float* __restrict__ u, const float* __restrict__ b_in)
{
    const int b     = blockIdx.x >> 3;
    const int chunk = blockIdx.x & 7;
    const int warp  = threadIdx.x >> 5;
    const int lane  = threadIdx.x & 31;
    const int wc    = chunk * 8 + warp;         // 0..63 within batch
    const int g     = lane >> 2;                // 0..7
    const unsigned FULL = 0xffffffffu;

    // v for the 4 (o,d4) slots this lane owns; layout matches coalesced u load:
    // slot j covers o = j*8 + g, d = (lane&3)*4 .. +3  -> float offset 128*j + 4*lane
    float4 v4[4];
    if (AGREE) {
        const float* vb = g_v + (size_t)b * ROW;
        #pragma unroll
        for (int j = 0; j < 4; ++j)
            v4[j] = *reinterpret_cast<const float4*>(vb + j * 128 + lane * 4);
    }

    float4 acc[4];
    #pragma unroll
    for (int j = 0; j < 4; ++j) acc[j] = make_float4(0.f, 0.f, 0.f, 0.f);

    const size_t ubase = ((size_t)b * IC + (size_t)wc * I_PER_WARP) * ROW;

    for (int ii = 0; ii < I_PER_WARP; ++ii) {
        const int i = wc * I_PER_WARP + ii;
        const float4* up = reinterpret_cast<const float4*>(u + ubase + (size_t)ii * ROW);

        float4 u4[4];
        #pragma unroll
        for (int j = 0; j < 4; ++j) u4[j] = up[j * 32 + lane];   // fully coalesced 2KB

        float logit[4];
        if (AGREE) {
            // lane l reads b for o = l (coalesced), shuffled to owners below
            float bv = BSRC_BATCHED ? g_bb[((size_t)b * IC + i) * OC + lane]
                                    : b_in[(size_t)i * OC + lane];
            #pragma unroll
            for (int j = 0; j < 4; ++j) {
                float p = u4[j].x * v4[j].x + u4[j].y * v4[j].y
                        + u4[j].z * v4[j].z + u4[j].w * v4[j].w;
                // reduce the 4 d-chunks (lanes sharing l>>2)
                p += __shfl_xor_sync(FULL, p, 1);
                p += __shfl_xor_sync(FULL, p, 2);
                float bl = __shfl_sync(FULL, bv, j * 8 + g);
                logit[j] = bl + p;
            }
            if (WRITE_B) {
                // lane l writes b[o=l]: value is logit[l>>3] held at lane (l&7)*4
                int src = (lane & 7) * 4;
                float t0 = __shfl_sync(FULL, logit[0], src);
                float t1 = __shfl_sync(FULL, logit[1], src);
                float t2 = __shfl_sync(FULL, logit[2], src);
                float t3 = __shfl_sync(FULL, logit[3], src);
                int sel = lane >> 3;
                float bnew = (sel == 0) ? t0 : (sel == 1) ? t1 : (sel == 2) ? t2 : t3;
                g_bb[((size_t)b * IC + i) * OC + lane] = bnew;
            }
        } else {
            float bv = b_in[(size_t)i * OC + lane];
            #pragma unroll
            for (int j = 0; j < 4; ++j)
                logit[j] = __shfl_sync(FULL, bv, j * 8 + g);
        }

        // softmax over the 32 output caps (each l&3 slice holds all 32 exactly once)
        float m = fmaxf(fmaxf(logit[0], logit[1]), fmaxf(logit[2], logit[3]));
        m = fmaxf(m, __shfl_xor_sync(FULL, m, 4));
        m = fmaxf(m, __shfl_xor_sync(FULL, m, 8));
        m = fmaxf(m, __shfl_xor_sync(FULL, m, 16));
        float e[4], Z = 0.f;
        #pragma unroll
        for (int j = 0; j < 4; ++j) { e[j] = __expf(logit[j] - m); Z += e[j]; }
        Z += __shfl_xor_sync(FULL, Z, 4);
        Z += __shfl_xor_sync(FULL, Z, 8);
        Z += __shfl_xor_sync(FULL, Z, 16);
        float rZ = __frcp_rn(Z);
        #pragma unroll
        for (int j = 0; j < 4; ++j) {
            float c = e[j] * rZ;
            acc[j].x += c * u4[j].x;
            acc[j].y += c * u4[j].y;
            acc[j].z += c * u4[j].z;
            acc[j].w += c * u4[j].w;
        }
    }

    // per-warp partial s, coalesced float4 store (offset 128*j + 4*lane floats)
    float4* pp = reinterpret_cast<float4*>(g_partial + ((size_t)b * WARPS_PER_BATCH + wc) * ROW);
    #pragma unroll
    for (int j = 0; j < 4; ++j) pp[j * 32 + lane] = acc[j];
}

// Deterministic 64-way reduction of partials + squash. 1 block per batch,
// 512 threads: tid -> (o = tid/16, d = tid%16).
template<bool TO_OUT>
__global__ __launch_bounds__(512)
void rba_squash(float* __restrict__ out)
{
    const int b  = blockIdx.x;
    const int od = threadIdx.x;
    const float* p = g_partial + (size_t)b * WARPS_PER_BATCH * ROW + od;

    float s0 = 0.f, s1 = 0.f, s2 = 0.f, s3 = 0.f;
    #pragma unroll
    for (int w = 0; w < WARPS_PER_BATCH; w += 4) {
        s0 += p[(size_t)(w + 0) * ROW];
        s1 += p[(size_t)(w + 1) * ROW];
        s2 += p[(size_t)(w + 2) * ROW];
        s3 += p[(size_t)(w + 3) * ROW];
    }
    float s = (s0 + s1) + (s2 + s3);

    const unsigned FULL = 0xffffffffu;
    float sq = s * s;
    sq += __shfl_xor_sync(FULL, sq, 1);
    sq += __shfl_xor_sync(FULL, sq, 2);
    sq += __shfl_xor_sync(FULL, sq, 4);
    sq += __shfl_xor_sync(FULL, sq, 8);   // ||s||^2 over the 16 d-lanes of this o

    float val = s * sqrtf(sq) / (1.0f + sq);
    float* dst = TO_OUT ? out : g_v;
    dst[(size_t)b * ROW + od] = val;
}

extern "C" void kernel_launch(void* const* d_in, const int* in_sizes, int n_in,
                              void* d_out, int out_size)
{
    const float* u   = (const float*)d_in[0];  // [128,2048,32,16]
    const float* bin = (const float*)d_in[1];  // [2048,32]
    float* out = (float*)d_out;                // [128,32,16]

    const dim3 grid(BATCH * BLOCKS_PER_BATCH);

    // init pass: c = softmax(b), s = sum_i c*u, v = squash(s)
    rba_compute_s<false, false, false><<<grid, THREADS>>>(u, bin);
    rba_squash<false><<<BATCH, 512>>>(out);

    // iteration 1: bsrc = b (broadcast), write g_bb
    rba_compute_s<true, false, true><<<grid, THREADS>>>(u, bin);
    rba_squash<false><<<BATCH, 512>>>(out);

    // iteration 2: bsrc = g_bb, write g_bb
    rba_compute_s<true, true, true><<<grid, THREADS>>>(u, bin);
    rba_squash<false><<<BATCH, 512>>>(out);

    // iteration 3 (last): bsrc = g_bb, skip dead b write, squash -> d_out
    rba_compute_s<true, true, false><<<grid, THREADS>>>(u, bin);
    rba_squash<true><<<BATCH, 512>>>(out);

    (void)in_sizes; (void)n_in; (void)out_size;
}

// round 2
// speedup vs baseline: 1.2119x; 1.2119x over previous
#include <cuda_runtime.h>
#include <cuda_fp16.h>

// Problem constants (fixed by setup_inputs)
#define BATCH 128
#define IC    2048
#define OC    32
#define OD    16
#define ROW   512          // OC*OD floats per (b,i) row
#define THREADS 256
#define WPB   8            // warps per block
#define BPB   8            // blocks per batch
#define WARPS_PER_BATCH 64
#define IPW   32           // IC / WARPS_PER_BATCH

// Scratch (device globals: allocation-free per harness rules)
__device__ __align__(16) __half g_u16[(size_t)BATCH * IC * ROW];   // 268 MB fp16 copy of u
__device__ __align__(16) float  g_part[(size_t)BATCH * BPB * ROW]; // 2 MB block partials
__device__ __align__(16) float  g_vsum[(size_t)BATCH * ROW];       // 256 KB running v sum
__device__ int g_cnt[BATCH];                                       // zero-init; self-resetting

// Block tail: in-block reduce 8 warp-accumulators -> 1 partial; last block per
// batch does the deterministic 8-way cross-block sum + squash.
// mode 0: vsum  = v   (init pass)
// mode 1: vsum += v   (intermediate iterations)
// mode 2: out   = v   (final iteration)
__device__ __forceinline__ void block_tail(const float4 acc[4], int b, int chunk,
                                           int warp, int lane, int mode,
                                           float* __restrict__ out)
{
    __shared__ float sred[WPB][ROW];   // 16 KB
    __shared__ bool amLast;

    #pragma unroll
    for (int j = 0; j < 4; ++j)
        *reinterpret_cast<float4*>(&sred[warp][j * 128 + lane * 4]) = acc[j];
    __syncthreads();

    const int t = threadIdx.x;
    float r0 = 0.f, r1 = 0.f;
    #pragma unroll
    for (int w = 0; w < WPB; ++w) { r0 += sred[w][t]; r1 += sred[w][t + 256]; }
    float* bp = g_part + ((size_t)b * BPB + chunk) * ROW;
    bp[t] = r0; bp[t + 256] = r1;

    __threadfence();
    __syncthreads();
    if (t == 0) {
        int old = atomicAdd(&g_cnt[b], 1);
        amLast = (old == BPB - 1);
        if (amLast) g_cnt[b] = 0;      // replay-safe reset
    }
    __syncthreads();
    if (!amLast) return;
    __threadfence();                   // acquire: see all blocks' partials

    const float* pb = g_part + (size_t)b * BPB * ROW;
    float s0 = 0.f, s1 = 0.f;
    #pragma unroll
    for (int c = 0; c < BPB; ++c) {    // fixed order -> deterministic
        s0 += pb[(size_t)c * ROW + t];
        s1 += pb[(size_t)c * ROW + t + 256];
    }

    // squash: ||s||^2 over the 16 d-lanes of each o (lanes 0-15 / 16-31 per o)
    const unsigned FULL = 0xffffffffu;
    float q0 = s0 * s0, q1 = s1 * s1;
    #pragma unroll
    for (int m = 1; m < 16; m <<= 1) {
        q0 += __shfl_xor_sync(FULL, q0, m);
        q1 += __shfl_xor_sync(FULL, q1, m);
    }
    float v0 = s0 * sqrtf(q0) / (1.f + q0);
    float v1 = s1 * sqrtf(q1) / (1.f + q1);

    float* vs = g_vsum + (size_t)b * ROW;
    if (mode == 0)      { vs[t] = v0;            vs[t + 256] = v1; }
    else if (mode == 1) { vs[t] += v0;           vs[t + 256] += v1; }
    else                { out[(size_t)b * ROW + t] = v0;
                          out[(size_t)b * ROW + t + 256] = v1; }
}

// Init pass: c = softmax(b_in) (no agreement), s = sum_i c*u.
// Also converts u -> fp16 copy for the later passes.
__global__ __launch_bounds__(THREADS)
void rba_init(const float* __restrict__ u, const float* __restrict__ bin)
{
    const int b     = blockIdx.x >> 3;
    const int chunk = blockIdx.x & 7;
    const int warp  = threadIdx.x >> 5;
    const int lane  = threadIdx.x & 31;
    const int g     = lane >> 2;
    const int wc    = chunk * WPB + warp;
    const unsigned FULL = 0xffffffffu;

    float4 acc[4];
    #pragma unroll
    for (int j = 0; j < 4; ++j) acc[j] = make_float4(0.f, 0.f, 0.f, 0.f);

    const size_t ubase = ((size_t)b * IC + (size_t)wc * IPW) * ROW;

    for (int ii = 0; ii < IPW; ++ii) {
        const int i = wc * IPW + ii;
        const float4* up = reinterpret_cast<const float4*>(u + ubase + (size_t)ii * ROW);
        __half* dst = g_u16 + ubase + (size_t)ii * ROW;

        float4 u4[4];
        #pragma unroll
        for (int j = 0; j < 4; ++j) u4[j] = up[j * 32 + lane];   // coalesced 2KB/row

        // write fp16 copy (coalesced 8B per lane per slot)
        #pragma unroll
        for (int j = 0; j < 4; ++j) {
            union { uint2 raw; __half2 h[2]; } pk;
            pk.h[0] = __floats2half2_rn(u4[j].x, u4[j].y);
            pk.h[1] = __floats2half2_rn(u4[j].z, u4[j].w);
            *reinterpret_cast<uint2*>(dst + j * 128 + lane * 4) = pk.raw;
        }

        // c = softmax(bin[i,:]) broadcast to slot owners
        float bv = bin[(size_t)i * OC + lane];
        float logit[4];
        #pragma unroll
        for (int j = 0; j < 4; ++j) logit[j] = __shfl_sync(FULL, bv, j * 8 + g);

        float m = fmaxf(fmaxf(logit[0], logit[1]), fmaxf(logit[2], logit[3]));
        m = fmaxf(m, __shfl_xor_sync(FULL, m, 4));
        m = fmaxf(m, __shfl_xor_sync(FULL, m, 8));
        m = fmaxf(m, __shfl_xor_sync(FULL, m, 16));
        float e[4], Z = 0.f;
        #pragma unroll
        for (int j = 0; j < 4; ++j) { e[j] = __expf(logit[j] - m); Z += e[j]; }
        Z += __shfl_xor_sync(FULL, Z, 4);
        Z += __shfl_xor_sync(FULL, Z, 8);
        Z += __shfl_xor_sync(FULL, Z, 16);
        float rZ = __frcp_rn(Z);
        #pragma unroll
        for (int j = 0; j < 4; ++j) {
            float c = e[j] * rZ;
            acc[j].x += c * u4[j].x; acc[j].y += c * u4[j].y;
            acc[j].z += c * u4[j].z; acc[j].w += c * u4[j].w;
        }
    }

    block_tail(acc, b, chunk, warp, lane, /*mode=*/0, nullptr);
}

// Agreement pass: logits = bin + dot(u, vsum); c = softmax; s = sum_i c*u.
// Reads the fp16 copy of u. MODE 1: vsum += v. MODE 2: out = v.
template<int MODE>
__global__ __launch_bounds__(THREADS)
void rba_iter(const float* __restrict__ bin, float* __restrict__ out)
{
    const int b     = blockIdx.x >> 3;
    const int chunk = blockIdx.x & 7;
    const int warp  = threadIdx.x >> 5;
    const int lane  = threadIdx.x & 31;
    const int g     = lane >> 2;
    const int wc    = chunk * WPB + warp;
    const unsigned FULL = 0xffffffffu;

    // vsum slots this lane owns (layout matches u load): o=j*8+g, d=(lane&3)*4..+3
    float4 v4[4];
    {
        const float* vb = g_vsum + (size_t)b * ROW;
        #pragma unroll
        for (int j = 0; j < 4; ++j)
            v4[j] = *reinterpret_cast<const float4*>(vb + j * 128 + lane * 4);
    }

    float4 acc[4];
    #pragma unroll
    for (int j = 0; j < 4; ++j) acc[j] = make_float4(0.f, 0.f, 0.f, 0.f);

    const size_t ubase = ((size_t)b * IC + (size_t)wc * IPW) * ROW;

    for (int ii = 0; ii < IPW; ++ii) {
        const int i = wc * IPW + ii;
        const uint2* up2 = reinterpret_cast<const uint2*>(g_u16 + ubase + (size_t)ii * ROW);

        float4 u4[4];
        #pragma unroll
        for (int j = 0; j < 4; ++j) {
            union { uint2 raw; __half2 h[2]; } pk;
            pk.raw = up2[j * 32 + lane];               // coalesced 256B per slot
            float2 f0 = __half22float2(pk.h[0]);
            float2 f1 = __half22float2(pk.h[1]);
            u4[j] = make_float4(f0.x, f0.y, f1.x, f1.y);
        }

        float bv = bin[(size_t)i * OC + lane];         // L2-resident (256KB)
        float logit[4];
        #pragma unroll
        for (int j = 0; j < 4; ++j) {
            float p = u4[j].x * v4[j].x + u4[j].y * v4[j].y
                    + u4[j].z * v4[j].z + u4[j].w * v4[j].w;
            p += __shfl_xor_sync(FULL, p, 1);
            p += __shfl_xor_sync(FULL, p, 2);          // full d-sum within quad
            logit[j] = __shfl_sync(FULL, bv, j * 8 + g) + p;
        }

        float m = fmaxf(fmaxf(logit[0], logit[1]), fmaxf(logit[2], logit[3]));
        m = fmaxf(m, __shfl_xor_sync(FULL, m, 4));
        m = fmaxf(m, __shfl_xor_sync(FULL, m, 8));
        m = fmaxf(m, __shfl_xor_sync(FULL, m, 16));
        float e[4], Z = 0.f;
        #pragma unroll
        for (int j = 0; j < 4; ++j) { e[j] = __expf(logit[j] - m); Z += e[j]; }
        Z += __shfl_xor_sync(FULL, Z, 4);
        Z += __shfl_xor_sync(FULL, Z, 8);
        Z += __shfl_xor_sync(FULL, Z, 16);
        float rZ = __frcp_rn(Z);
        #pragma unroll
        for (int j = 0; j < 4; ++j) {
            float c = e[j] * rZ;
            acc[j].x += c * u4[j].x; acc[j].y += c * u4[j].y;
            acc[j].z += c * u4[j].z; acc[j].w += c * u4[j].w;
        }
    }

    block_tail(acc, b, chunk, warp, lane, MODE, out);
}

extern "C" void kernel_launch(void* const* d_in, const int* in_sizes, int n_in,
                              void* d_out, int out_size)
{
    const float* u   = (const float*)d_in[0];  // [128,2048,32,16] f32
    const float* bin = (const float*)d_in[1];  // [2048,32] f32
    float* out = (float*)d_out;                // [128,32,16] f32

    const dim3 grid(BATCH * BPB);

    // v0 = squash(sum c0*u), c0 = softmax(bin); also emit fp16 u; vsum = v0
    rba_init<<<grid, THREADS>>>(u, bin);
    // iter1: logits = bin + u.v0          ; vsum += v1
    rba_iter<1><<<grid, THREADS>>>(bin, out);
    // iter2: logits = bin + u.(v0+v1)     ; vsum += v2
    rba_iter<1><<<grid, THREADS>>>(bin, out);
    // iter3: logits = bin + u.(v0+v1+v2)  ; out = v3
    rba_iter<2><<<grid, THREADS>>>(bin, out);

    (void)in_sizes; (void)n_in; (void)out_size;
}

// round 3
// speedup vs baseline: 1.3432x; 1.1084x over previous
#include <cuda_runtime.h>
#include <cuda_fp16.h>

// Problem constants (fixed by setup_inputs)
#define BATCH 128
#define IC    2048
#define OC    32
#define OD    16
#define ROW   512          // OC*OD floats per (b,i) row
#define THREADS 256
#define WPB   8            // warps per block
#define BPB   8            // blocks per batch
#define IPW   32           // IC rows per warp

// Scratch (device globals: allocation-free per harness rules)
__device__ __align__(16) __half g_u16[(size_t)BATCH * IC * ROW];   // 268 MB fp16 copy of u
__device__ __align__(16) float  g_part[(size_t)BATCH * BPB * ROW]; // 2 MB block partials
__device__ __align__(16) float  g_vsum[(size_t)BATCH * ROW];       // 256 KB running v sum
__device__ int g_cnt[BATCH];                                       // zero-init; self-resetting

// Cross-block reduction + squash, after warp partials are in sred.
// mode 0: vsum = v; mode 1: vsum += v; mode 2: out = v.
__device__ __forceinline__ void block_tail_reduce(float (*sred)[ROW], int b, int chunk,
                                                  int mode, float* __restrict__ out)
{
    __shared__ bool amLast;
    const int t = threadIdx.x;
    float r0 = 0.f, r1 = 0.f;
    #pragma unroll
    for (int w = 0; w < WPB; ++w) { r0 += sred[w][t]; r1 += sred[w][t + 256]; }
    float* bp = g_part + ((size_t)b * BPB + chunk) * ROW;
    bp[t] = r0; bp[t + 256] = r1;

    __threadfence();
    __syncthreads();
    if (t == 0) {
        int old = atomicAdd(&g_cnt[b], 1);
        amLast = (old == BPB - 1);
        if (amLast) g_cnt[b] = 0;      // replay-safe reset
    }
    __syncthreads();
    if (!amLast) return;
    __threadfence();                   // acquire: see all blocks' partials

    const float* pb = g_part + (size_t)b * BPB * ROW;
    float s0 = 0.f, s1 = 0.f;
    #pragma unroll
    for (int c = 0; c < BPB; ++c) {    // fixed order -> deterministic
        s0 += pb[(size_t)c * ROW + t];
        s1 += pb[(size_t)c * ROW + t + 256];
    }

    // squash: ||s||^2 over the 16 d-lanes of each o
    const unsigned FULL = 0xffffffffu;
    float q0 = s0 * s0, q1 = s1 * s1;
    #pragma unroll
    for (int m = 1; m < 16; m <<= 1) {
        q0 += __shfl_xor_sync(FULL, q0, m);
        q1 += __shfl_xor_sync(FULL, q1, m);
    }
    float v0 = s0 * sqrtf(q0) / (1.f + q0);
    float v1 = s1 * sqrtf(q1) / (1.f + q1);

    float* vs = g_vsum + (size_t)b * ROW;
    if (mode == 0)      { vs[t] = v0;            vs[t + 256] = v1; }
    else if (mode == 1) { vs[t] += v0;           vs[t + 256] += v1; }
    else                { out[(size_t)b * ROW + t] = v0;
                          out[(size_t)b * ROW + t + 256] = v1; }
}

// Init pass: c = softmax(b_in) (no agreement), s = sum_i c*u.
// Also converts u -> fp16 copy for the later passes. (HBM-bound: 804 MB.)
__global__ __launch_bounds__(THREADS)
void rba_init(const float* __restrict__ u, const float* __restrict__ bin)
{
    __shared__ float sred[WPB][ROW];
    const int b     = blockIdx.x >> 3;
    const int chunk = blockIdx.x & 7;
    const int warp  = threadIdx.x >> 5;
    const int lane  = threadIdx.x & 31;
    const int g     = lane >> 2;
    const int wc    = chunk * WPB + warp;
    const unsigned FULL = 0xffffffffu;

    float4 acc[4];
    #pragma unroll
    for (int j = 0; j < 4; ++j) acc[j] = make_float4(0.f, 0.f, 0.f, 0.f);

    const size_t ubase = ((size_t)b * IC + (size_t)wc * IPW) * ROW;

    for (int ii = 0; ii < IPW; ++ii) {
        const int i = wc * IPW + ii;
        const float4* up = reinterpret_cast<const float4*>(u + ubase + (size_t)ii * ROW);
        __half* dst = g_u16 + ubase + (size_t)ii * ROW;

        float4 u4[4];
        #pragma unroll
        for (int j = 0; j < 4; ++j) u4[j] = up[j * 32 + lane];   // coalesced 2KB/row

        #pragma unroll
        for (int j = 0; j < 4; ++j) {
            union { uint2 raw; __half2 h[2]; } pk;
            pk.h[0] = __floats2half2_rn(u4[j].x, u4[j].y);
            pk.h[1] = __floats2half2_rn(u4[j].z, u4[j].w);
            *reinterpret_cast<uint2*>(dst + j * 128 + lane * 4) = pk.raw;
        }

        // c = softmax(bin[i,:]) broadcast to slot owners (o = j*8+g)
        float bv = bin[(size_t)i * OC + lane];
        float logit[4];
        #pragma unroll
        for (int j = 0; j < 4; ++j) logit[j] = __shfl_sync(FULL, bv, j * 8 + g);

        float e[4], Z = 0.f;
        #pragma unroll
        for (int j = 0; j < 4; ++j) { e[j] = __expf(logit[j]); Z += e[j]; }
        Z += __shfl_xor_sync(FULL, Z, 4);
        Z += __shfl_xor_sync(FULL, Z, 8);
        Z += __shfl_xor_sync(FULL, Z, 16);
        float rZ = __frcp_rn(Z);
        #pragma unroll
        for (int j = 0; j < 4; ++j) {
            float c = e[j] * rZ;
            acc[j].x += c * u4[j].x; acc[j].y += c * u4[j].y;
            acc[j].z += c * u4[j].z; acc[j].w += c * u4[j].w;
        }
    }

    #pragma unroll
    for (int j = 0; j < 4; ++j)
        *reinterpret_cast<float4*>(&sred[warp][j * 128 + lane * 4]) = acc[j];
    __syncthreads();
    block_tail_reduce(sred, b, chunk, /*mode=*/0, nullptr);
}

// Agreement pass: logits = bin + dot(u, vsum); c = softmax; s = sum_i c*u.
// fp16 u, LDG.128 layout: lane l owns oA=l/2, oB=16+l/2, d=(l&1)*8..+7.
// Depth-2 pipelined loads; no max-subtraction (|logit| << 88).
template<int MODE>
__global__ __launch_bounds__(THREADS)
void rba_iter(const float* __restrict__ bin, float* __restrict__ out)
{
    __shared__ float sred[WPB][ROW];
    const int b     = blockIdx.x >> 3;
    const int chunk = blockIdx.x & 7;
    const int warp  = threadIdx.x >> 5;
    const int lane  = threadIdx.x & 31;
    const int wc    = chunk * WPB + warp;
    const unsigned FULL = 0xffffffffu;

    // vsum slots: slot A floats [8*lane, 8*lane+8), slot B +256  (= o*16+d)
    float vA[8], vB[8];
    {
        const float* vb = g_vsum + (size_t)b * ROW + lane * 8;
        float4 a0 = *reinterpret_cast<const float4*>(vb);
        float4 a1 = *reinterpret_cast<const float4*>(vb + 4);
        float4 b0 = *reinterpret_cast<const float4*>(vb + 256);
        float4 b1 = *reinterpret_cast<const float4*>(vb + 260);
        vA[0]=a0.x; vA[1]=a0.y; vA[2]=a0.z; vA[3]=a0.w;
        vA[4]=a1.x; vA[5]=a1.y; vA[6]=a1.z; vA[7]=a1.w;
        vB[0]=b0.x; vB[1]=b0.y; vB[2]=b0.z; vB[3]=b0.w;
        vB[4]=b1.x; vB[5]=b1.y; vB[6]=b1.z; vB[7]=b1.w;
    }

    float accA[8], accB[8];
    #pragma unroll
    for (int k = 0; k < 8; ++k) { accA[k] = 0.f; accB[k] = 0.f; }

    const __half* up = g_u16 + ((size_t)b * IC + (size_t)wc * IPW) * ROW;
    const int loff = lane * 8;   // halves

    // depth-2 prefetch buffers (uint4 = 8 halves)
    uint4 bufA[2], bufB[2];
    bufA[0] = *reinterpret_cast<const uint4*>(up + loff);
    bufB[0] = *reinterpret_cast<const uint4*>(up + 256 + loff);
    bufA[1] = *reinterpret_cast<const uint4*>(up + ROW + loff);
    bufB[1] = *reinterpret_cast<const uint4*>(up + ROW + 256 + loff);

    const int src0 = lane >> 1;          // shfl source for bin broadcast

    #pragma unroll 2
    for (int ii = 0; ii < IPW; ++ii) {
        const int pf = (ii + 2 < IPW) ? (ii + 2) : (IPW - 1);   // clamped prefetch
        uint4 nA = *reinterpret_cast<const uint4*>(up + (size_t)pf * ROW + loff);
        uint4 nB = *reinterpret_cast<const uint4*>(up + (size_t)pf * ROW + 256 + loff);

        const uint4 rA = bufA[ii & 1];
        const uint4 rB = bufB[ii & 1];

        float uA[8], uB[8];
        {
            const __half2* hA = reinterpret_cast<const __half2*>(&rA);
            const __half2* hB = reinterpret_cast<const __half2*>(&rB);
            #pragma unroll
            for (int k = 0; k < 4; ++k) {
                float2 fa = __half22float2(hA[k]);
                float2 fb = __half22float2(hB[k]);
                uA[2*k] = fa.x; uA[2*k+1] = fa.y;
                uB[2*k] = fb.x; uB[2*k+1] = fb.y;
            }
        }

        float pA = 0.f, pB = 0.f;
        #pragma unroll
        for (int k = 0; k < 8; ++k) { pA += uA[k]*vA[k]; pB += uB[k]*vB[k]; }
        pA += __shfl_xor_sync(FULL, pA, 1);   // full d-dot within lane pair
        pB += __shfl_xor_sync(FULL, pB, 1);

        const int i = wc * IPW + ii;
        float bv  = bin[(size_t)i * OC + lane];          // L2-resident
        float blA = __shfl_sync(FULL, bv, src0);
        float blB = __shfl_sync(FULL, bv, 16 + src0);

        float eA = __expf(blA + pA);
        float eB = __expf(blB + pB);
        float Z  = eA + eB;
        // xor{2,4,8,16} sums each of the 32 output caps exactly once
        Z += __shfl_xor_sync(FULL, Z, 2);
        Z += __shfl_xor_sync(FULL, Z, 4);
        Z += __shfl_xor_sync(FULL, Z, 8);
        Z += __shfl_xor_sync(FULL, Z, 16);
        float rZ = __frcp_rn(Z);
        float cA = eA * rZ, cB = eB * rZ;

        #pragma unroll
        for (int k = 0; k < 8; ++k) { accA[k] += cA*uA[k]; accB[k] += cB*uB[k]; }

        bufA[ii & 1] = nA;
        bufB[ii & 1] = nB;
    }

    // warp partials -> sred at s-index o*16+d = 8*lane (+256 for slot B)
    float* w0 = &sred[warp][lane * 8];
    *reinterpret_cast<float4*>(w0)       = make_float4(accA[0],accA[1],accA[2],accA[3]);
    *reinterpret_cast<float4*>(w0 + 4)   = make_float4(accA[4],accA[5],accA[6],accA[7]);
    *reinterpret_cast<float4*>(w0 + 256) = make_float4(accB[0],accB[1],accB[2],accB[3]);
    *reinterpret_cast<float4*>(w0 + 260) = make_float4(accB[4],accB[5],accB[6],accB[7]);
    __syncthreads();
    block_tail_reduce(sred, b, chunk, MODE, out);
}

extern "C" void kernel_launch(void* const* d_in, const int* in_sizes, int n_in,
                              void* d_out, int out_size)
{
    const float* u   = (const float*)d_in[0];  // [128,2048,32,16] f32
    const float* bin = (const float*)d_in[1];  // [2048,32] f32
    float* out = (float*)d_out;                // [128,32,16] f32

    const dim3 grid(BATCH * BPB);

    // v0 = squash(sum c0*u), c0 = softmax(bin); emit fp16 u; vsum = v0
    rba_init<<<grid, THREADS>>>(u, bin);
    // iter1: logits = bin + u.v0          ; vsum += v1
    rba_iter<1><<<grid, THREADS>>>(bin, out);
    // iter2: logits = bin + u.(v0+v1)     ; vsum += v2
    rba_iter<1><<<grid, THREADS>>>(bin, out);
    // iter3: logits = bin + u.(v0+v1+v2)  ; out = v3
    rba_iter<2><<<grid, THREADS>>>(bin, out);

    (void)in_sizes; (void)n_in; (void)out_size;
}

// round 5
// speedup vs baseline: 1.4211x; 1.0580x over previous
#include <cuda_runtime.h>
#include <cuda_fp16.h>
#include <cstdint>

// Problem constants (fixed by setup_inputs)
#define BATCH 128
#define IC    2048
#define OC    32
#define OD    16
#define ROW   512          // OC*OD floats per (b,i) row
#define THREADS 256
#define WPB   8            // warps per block
#define BPB   8            // blocks per batch
#define IPW   32           // IC rows per warp
#define DEPTH 4            // smem staging ring depth (rows)

// Scratch (device globals: allocation-free per harness rules)
__device__ __align__(16) __half g_u16[(size_t)BATCH * IC * ROW];   // 268 MB fp16 copy of u
__device__ __align__(16) float  g_part[(size_t)BATCH * BPB * ROW]; // 2 MB block partials
__device__ __align__(16) float  g_vsum[(size_t)BATCH * ROW];       // 256 KB running v sum
__device__ int g_cnt[BATCH];                                       // zero-init; self-resetting

__device__ __forceinline__ void cp_async16(unsigned saddr, const void* gptr) {
    asm volatile("cp.async.cg.shared.global [%0], [%1], 16;\n"
                 :: "r"(saddr), "l"(gptr) : "memory");
}

// Cross-block reduction + squash, after warp partials are in sred.
// mode 0: vsum = v; mode 1: vsum += v; mode 2: out = v.
__device__ __forceinline__ void block_tail_reduce(float (*sred)[ROW], int b, int chunk,
                                                  int mode, float* __restrict__ out)
{
    __shared__ bool amLast;
    const int t = threadIdx.x;
    float r0 = 0.f, r1 = 0.f;
    #pragma unroll
    for (int w = 0; w < WPB; ++w) { r0 += sred[w][t]; r1 += sred[w][t + 256]; }
    float* bp = g_part + ((size_t)b * BPB + chunk) * ROW;
    bp[t] = r0; bp[t + 256] = r1;

    __threadfence();
    __syncthreads();
    if (t == 0) {
        int old = atomicAdd(&g_cnt[b], 1);
        amLast = (old == BPB - 1);
        if (amLast) g_cnt[b] = 0;      // replay-safe reset
    }
    __syncthreads();
    if (!amLast) return;
    __threadfence();                   // acquire: see all blocks' partials

    const float* pb = g_part + (size_t)b * BPB * ROW;
    float s0 = 0.f, s1 = 0.f;
    #pragma unroll
    for (int c = 0; c < BPB; ++c) {    // fixed order -> deterministic
        s0 += pb[(size_t)c * ROW + t];
        s1 += pb[(size_t)c * ROW + t + 256];
    }

    // squash: ||s||^2 over the 16 d-lanes of each o
    const unsigned FULL = 0xffffffffu;
    float q0 = s0 * s0, q1 = s1 * s1;
    #pragma unroll
    for (int m = 1; m < 16; m <<= 1) {
        q0 += __shfl_xor_sync(FULL, q0, m);
        q1 += __shfl_xor_sync(FULL, q1, m);
    }
    float v0 = s0 * sqrtf(q0) / (1.f + q0);
    float v1 = s1 * sqrtf(q1) / (1.f + q1);

    float* vs = g_vsum + (size_t)b * ROW;
    if (mode == 0)      { vs[t] = v0;            vs[t + 256] = v1; }
    else if (mode == 1) { vs[t] += v0;           vs[t + 256] += v1; }
    else                { out[(size_t)b * ROW + t] = v0;
                          out[(size_t)b * ROW + t + 256] = v1; }
}

// Init pass: c = softmax(b_in), s = sum_i c*u; emits fp16 copy of u.
// HBM-bound (804 MB) and already at ~7 TB/s — unchanged.
__global__ __launch_bounds__(THREADS)
void rba_init(const float* __restrict__ u, const float* __restrict__ bin)
{
    __shared__ float sred[WPB][ROW];
    const int b     = blockIdx.x >> 3;
    const int chunk = blockIdx.x & 7;
    const int warp  = threadIdx.x >> 5;
    const int lane  = threadIdx.x & 31;
    const int g     = lane >> 2;
    const int wc    = chunk * WPB + warp;
    const unsigned FULL = 0xffffffffu;

    float4 acc[4];
    #pragma unroll
    for (int j = 0; j < 4; ++j) acc[j] = make_float4(0.f, 0.f, 0.f, 0.f);

    const size_t ubase = ((size_t)b * IC + (size_t)wc * IPW) * ROW;

    for (int ii = 0; ii < IPW; ++ii) {
        const int i = wc * IPW + ii;
        const float4* up = reinterpret_cast<const float4*>(u + ubase + (size_t)ii * ROW);
        __half* dst = g_u16 + ubase + (size_t)ii * ROW;

        float4 u4[4];
        #pragma unroll
        for (int j = 0; j < 4; ++j) u4[j] = up[j * 32 + lane];   // coalesced 2KB/row

        #pragma unroll
        for (int j = 0; j < 4; ++j) {
            union { uint2 raw; __half2 h[2]; } pk;
            pk.h[0] = __floats2half2_rn(u4[j].x, u4[j].y);
            pk.h[1] = __floats2half2_rn(u4[j].z, u4[j].w);
            *reinterpret_cast<uint2*>(dst + j * 128 + lane * 4) = pk.raw;
        }

        float bv = bin[(size_t)i * OC + lane];
        float logit[4];
        #pragma unroll
        for (int j = 0; j < 4; ++j) logit[j] = __shfl_sync(FULL, bv, j * 8 + g);

        float e[4], Z = 0.f;
        #pragma unroll
        for (int j = 0; j < 4; ++j) { e[j] = __expf(logit[j]); Z += e[j]; }
        Z += __shfl_xor_sync(FULL, Z, 4);
        Z += __shfl_xor_sync(FULL, Z, 8);
        Z += __shfl_xor_sync(FULL, Z, 16);
        float rZ = __frcp_rn(Z);
        #pragma unroll
        for (int j = 0; j < 4; ++j) {
            float c = e[j] * rZ;
            acc[j].x += c * u4[j].x; acc[j].y += c * u4[j].y;
            acc[j].z += c * u4[j].z; acc[j].w += c * u4[j].w;
        }
    }

    #pragma unroll
    for (int j = 0; j < 4; ++j)
        *reinterpret_cast<float4*>(&sred[warp][j * 128 + lane * 4]) = acc[j];
    __syncthreads();
    block_tail_reduce(sred, b, chunk, /*mode=*/0, nullptr);
}

// Agreement pass: logits = bin + dot(u, vsum); c = softmax; s = sum_i c*u.
// fp16 u via cp.async 4-deep smem ring (each lane copies exactly the 32B it
// reads back -> per-thread wait_group, no barriers in loop). sred aliases the
// stage buffer (dead after the loop) to keep smem at 32KB, 3 blocks/SM.
template<int MODE>
__global__ __launch_bounds__(THREADS, 3)
void rba_iter(const float* __restrict__ bin, float* __restrict__ out)
{
    __shared__ __align__(16) char smem_raw[WPB * DEPTH * ROW * 2];   // 32 KB
    __half (*stage)[DEPTH][ROW] = reinterpret_cast<__half(*)[DEPTH][ROW]>(smem_raw);
    float  (*sred)[ROW]         = reinterpret_cast<float(*)[ROW]>(smem_raw);

    const int b     = blockIdx.x >> 3;
    const int chunk = blockIdx.x & 7;
    const int warp  = threadIdx.x >> 5;
    const int lane  = threadIdx.x & 31;
    const int wc    = chunk * WPB + warp;
    const unsigned FULL = 0xffffffffu;

    // vsum slots: slot A floats [8*lane, +8), slot B +256  (= o*16+d)
    float vA[8], vB[8];
    {
        const float* vb = g_vsum + (size_t)b * ROW + lane * 8;
        float4 a0 = *reinterpret_cast<const float4*>(vb);
        float4 a1 = *reinterpret_cast<const float4*>(vb + 4);
        float4 b0 = *reinterpret_cast<const float4*>(vb + 256);
        float4 b1 = *reinterpret_cast<const float4*>(vb + 260);
        vA[0]=a0.x; vA[1]=a0.y; vA[2]=a0.z; vA[3]=a0.w;
        vA[4]=a1.x; vA[5]=a1.y; vA[6]=a1.z; vA[7]=a1.w;
        vB[0]=b0.x; vB[1]=b0.y; vB[2]=b0.z; vB[3]=b0.w;
        vB[4]=b1.x; vB[5]=b1.y; vB[6]=b1.z; vB[7]=b1.w;
    }

    float accA[8], accB[8];
    #pragma unroll
    for (int k = 0; k < 8; ++k) { accA[k] = 0.f; accB[k] = 0.f; }

    const __half* up = g_u16 + ((size_t)b * IC + (size_t)wc * IPW) * ROW;
    const int loff = lane * 8;                 // halves
    const int src0 = lane >> 1;                // shfl source for bin broadcast

    const unsigned sbase =
        (unsigned)__cvta_generic_to_shared(&stage[warp][0][0]) + loff * 2;

    // prologue: rows 0..2 in flight (3 groups)
    #pragma unroll
    for (int p = 0; p < 3; ++p) {
        const __half* g = up + (size_t)p * ROW + loff;
        cp_async16(sbase + p * (ROW * 2), g);
        cp_async16(sbase + p * (ROW * 2) + 512, g + 256);
        asm volatile("cp.async.commit_group;\n" ::: "memory");
    }

    #pragma unroll 4
    for (int ii = 0; ii < IPW; ++ii) {
        asm volatile("cp.async.wait_group 2;\n" ::: "memory");   // row ii ready

        const int pf = ii + 3;
        if (pf < IPW) {
            const __half* g = up + (size_t)pf * ROW + loff;
            const unsigned sa = sbase + (pf & (DEPTH - 1)) * (ROW * 2);
            cp_async16(sa, g);
            cp_async16(sa + 512, g + 256);
        }
        asm volatile("cp.async.commit_group;\n" ::: "memory");

        const int s = ii & (DEPTH - 1);
        uint4 rA = *reinterpret_cast<const uint4*>(&stage[warp][s][loff]);
        uint4 rB = *reinterpret_cast<const uint4*>(&stage[warp][s][256 + loff]);

        float uA[8], uB[8];
        {
            const __half2* hA = reinterpret_cast<const __half2*>(&rA);
            const __half2* hB = reinterpret_cast<const __half2*>(&rB);
            #pragma unroll
            for (int k = 0; k < 4; ++k) {
                float2 fa = __half22float2(hA[k]);
                float2 fb = __half22float2(hB[k]);
                uA[2*k] = fa.x; uA[2*k+1] = fa.y;
                uB[2*k] = fb.x; uB[2*k+1] = fb.y;
            }
        }

        float pA = 0.f, pB = 0.f;
        #pragma unroll
        for (int k = 0; k < 8; ++k) { pA += uA[k]*vA[k]; pB += uB[k]*vB[k]; }
        pA += __shfl_xor_sync(FULL, pA, 1);   // full d-dot within lane pair
        pB += __shfl_xor_sync(FULL, pB, 1);

        const int i = wc * IPW + ii;
        float bv  = bin[(size_t)i * OC + lane];          // L2-resident
        float blA = __shfl_sync(FULL, bv, src0);
        float blB = __shfl_sync(FULL, bv, 16 + src0);

        float eA = __expf(blA + pA);
        float eB = __expf(blB + pB);
        float Z  = eA + eB;
        // xor{2,4,8,16} sums each of the 32 output caps exactly once
        Z += __shfl_xor_sync(FULL, Z, 2);
        Z += __shfl_xor_sync(FULL, Z, 4);
        Z += __shfl_xor_sync(FULL, Z, 8);
        Z += __shfl_xor_sync(FULL, Z, 16);
        float rZ = __frcp_rn(Z);
        float cA = eA * rZ, cB = eB * rZ;

        #pragma unroll
        for (int k = 0; k < 8; ++k) { accA[k] += cA*uA[k]; accB[k] += cB*uB[k]; }
    }

    asm volatile("cp.async.wait_group 0;\n" ::: "memory");
    __syncthreads();                       // stage dead; safe to alias as sred

    float* w0 = &sred[warp][lane * 8];
    *reinterpret_cast<float4*>(w0)       = make_float4(accA[0],accA[1],accA[2],accA[3]);
    *reinterpret_cast<float4*>(w0 + 4)   = make_float4(accA[4],accA[5],accA[6],accA[7]);
    *reinterpret_cast<float4*>(w0 + 256) = make_float4(accB[0],accB[1],accB[2],accB[3]);
    *reinterpret_cast<float4*>(w0 + 260) = make_float4(accB[4],accB[5],accB[6],accB[7]);
    __syncthreads();
    block_tail_reduce(sred, b, chunk, MODE, out);
}

extern "C" void kernel_launch(void* const* d_in, const int* in_sizes, int n_in,
                              void* d_out, int out_size)
{
    const float* u   = (const float*)d_in[0];  // [128,2048,32,16] f32
    const float* bin = (const float*)d_in[1];  // [2048,32] f32
    float* out = (float*)d_out;                // [128,32,16] f32

    const dim3 grid(BATCH * BPB);

    // v0 = squash(sum c0*u), c0 = softmax(bin); emit fp16 u; vsum = v0
    rba_init<<<grid, THREADS>>>(u, bin);
    // iter1: logits = bin + u.v0          ; vsum += v1
    rba_iter<1><<<grid, THREADS>>>(bin, out);
    // iter2: logits = bin + u.(v0+v1)     ; vsum += v2
    rba_iter<1><<<grid, THREADS>>>(bin, out);
    // iter3: logits = bin + u.(v0+v1+v2)  ; out = v3
    rba_iter<2><<<grid, THREADS>>>(bin, out);

    (void)in_sizes; (void)n_in; (void)out_size;
}

// round 6
// speedup vs baseline: 1.5286x; 1.0756x over previous
#include <cuda_runtime.h>
#include <cuda_fp16.h>
#include <cstdint>

// Problem constants (fixed by setup_inputs)
#define BATCH 128
#define IC    2048
#define OC    32
#define OD    16
#define ROW   512          // OC*OD floats per (b,i) row
#define THREADS 256
#define WPB   8            // warps per block
#define BPB   8            // blocks per batch
#define IPW   32           // IC rows per warp
#define DEPTH 4            // smem staging ring depth (rows)

typedef unsigned long long u64;

// Scratch (device globals: allocation-free per harness rules)
__device__ __align__(16) __half g_u16[(size_t)BATCH * IC * ROW];   // 268 MB fp16 copy of u
__device__ __align__(16) float  g_part[(size_t)BATCH * BPB * ROW]; // 2 MB block partials
__device__ __align__(16) float  g_vsum[(size_t)BATCH * ROW];       // 256 KB running v sum
__device__ int g_cnt[BATCH];                                       // zero-init; self-resetting

__device__ __forceinline__ void cp_async16(unsigned saddr, const void* gptr) {
    asm volatile("cp.async.cg.shared.global [%0], [%1], 16;\n"
                 :: "r"(saddr), "l"(gptr) : "memory");
}
// Packed f32x2 helpers (sm_103a FFMA2 path)
__device__ __forceinline__ u64 pack_f2(float lo, float hi) {
    u64 r; asm("mov.b64 %0, {%1, %2};" : "=l"(r) : "f"(lo), "f"(hi)); return r;
}
__device__ __forceinline__ void unpack_f2(u64 v, float& lo, float& hi) {
    asm("mov.b64 {%0, %1}, %2;" : "=f"(lo), "=f"(hi) : "l"(v));
}
__device__ __forceinline__ void ffma2(u64& d, u64 a, u64 b) {
    asm("fma.rn.f32x2 %0, %1, %2, %0;" : "+l"(d) : "l"(a), "l"(b));
}

// Cross-block reduction + squash, after warp partials are in sred.
// mode 0: vsum = v; mode 1: vsum += v; mode 2: out = v.
__device__ __forceinline__ void block_tail_reduce(float (*sred)[ROW], int b, int chunk,
                                                  int mode, float* __restrict__ out)
{
    __shared__ bool amLast;
    const int t = threadIdx.x;
    float r0 = 0.f, r1 = 0.f;
    #pragma unroll
    for (int w = 0; w < WPB; ++w) { r0 += sred[w][t]; r1 += sred[w][t + 256]; }
    float* bp = g_part + ((size_t)b * BPB + chunk) * ROW;
    bp[t] = r0; bp[t + 256] = r1;

    __threadfence();
    __syncthreads();
    if (t == 0) {
        int old = atomicAdd(&g_cnt[b], 1);
        amLast = (old == BPB - 1);
        if (amLast) g_cnt[b] = 0;      // replay-safe reset
    }
    __syncthreads();
    if (!amLast) return;
    __threadfence();                   // acquire: see all blocks' partials

    const float* pb = g_part + (size_t)b * BPB * ROW;
    float s0 = 0.f, s1 = 0.f;
    #pragma unroll
    for (int c = 0; c < BPB; ++c) {    // fixed order -> deterministic
        s0 += pb[(size_t)c * ROW + t];
        s1 += pb[(size_t)c * ROW + t + 256];
    }

    // squash: ||s||^2 over the 16 d-lanes of each o
    const unsigned FULL = 0xffffffffu;
    float q0 = s0 * s0, q1 = s1 * s1;
    #pragma unroll
    for (int m = 1; m < 16; m <<= 1) {
        q0 += __shfl_xor_sync(FULL, q0, m);
        q1 += __shfl_xor_sync(FULL, q1, m);
    }
    float v0 = s0 * sqrtf(q0) / (1.f + q0);
    float v1 = s1 * sqrtf(q1) / (1.f + q1);

    float* vs = g_vsum + (size_t)b * ROW;
    if (mode == 0)      { vs[t] = v0;            vs[t + 256] = v1; }
    else if (mode == 1) { vs[t] += v0;           vs[t + 256] += v1; }
    else                { out[(size_t)b * ROW + t] = v0;
                          out[(size_t)b * ROW + t + 256] = v1; }
}

// Init pass: c = softmax(b_in), s = sum_i c*u; emits fp16 copy of u.
// HBM-bound (804 MB) at ~7.8 TB/s already — unchanged.
__global__ __launch_bounds__(THREADS)
void rba_init(const float* __restrict__ u, const float* __restrict__ bin)
{
    __shared__ float sred[WPB][ROW];
    const int b     = blockIdx.x >> 3;
    const int chunk = blockIdx.x & 7;
    const int warp  = threadIdx.x >> 5;
    const int lane  = threadIdx.x & 31;
    const int g     = lane >> 2;
    const int wc    = chunk * WPB + warp;
    const unsigned FULL = 0xffffffffu;

    float4 acc[4];
    #pragma unroll
    for (int j = 0; j < 4; ++j) acc[j] = make_float4(0.f, 0.f, 0.f, 0.f);

    const size_t ubase = ((size_t)b * IC + (size_t)wc * IPW) * ROW;

    for (int ii = 0; ii < IPW; ++ii) {
        const int i = wc * IPW + ii;
        const float4* up = reinterpret_cast<const float4*>(u + ubase + (size_t)ii * ROW);
        __half* dst = g_u16 + ubase + (size_t)ii * ROW;

        float4 u4[4];
        #pragma unroll
        for (int j = 0; j < 4; ++j) u4[j] = up[j * 32 + lane];   // coalesced 2KB/row

        #pragma unroll
        for (int j = 0; j < 4; ++j) {
            union { uint2 raw; __half2 h[2]; } pk;
            pk.h[0] = __floats2half2_rn(u4[j].x, u4[j].y);
            pk.h[1] = __floats2half2_rn(u4[j].z, u4[j].w);
            *reinterpret_cast<uint2*>(dst + j * 128 + lane * 4) = pk.raw;
        }

        float bv = bin[(size_t)i * OC + lane];
        float logit[4];
        #pragma unroll
        for (int j = 0; j < 4; ++j) logit[j] = __shfl_sync(FULL, bv, j * 8 + g);

        float e[4], Z = 0.f;
        #pragma unroll
        for (int j = 0; j < 4; ++j) { e[j] = __expf(logit[j]); Z += e[j]; }
        Z += __shfl_xor_sync(FULL, Z, 4);
        Z += __shfl_xor_sync(FULL, Z, 8);
        Z += __shfl_xor_sync(FULL, Z, 16);
        float rZ = __frcp_rn(Z);
        #pragma unroll
        for (int j = 0; j < 4; ++j) {
            float c = e[j] * rZ;
            acc[j].x += c * u4[j].x; acc[j].y += c * u4[j].y;
            acc[j].z += c * u4[j].z; acc[j].w += c * u4[j].w;
        }
    }

    #pragma unroll
    for (int j = 0; j < 4; ++j)
        *reinterpret_cast<float4*>(&sred[warp][j * 128 + lane * 4]) = acc[j];
    __syncthreads();
    block_tail_reduce(sred, b, chunk, /*mode=*/0, nullptr);
}

// Agreement pass: logits = bin + dot(u, vsum); c = softmax; s = sum_i c*u.
// fp16 u via cp.async 4-deep smem ring; packed f32x2 FMA for dot + accum;
// sred aliases the stage buffer; 4 blocks/SM.
template<int MODE>
__global__ __launch_bounds__(THREADS, 4)
void rba_iter(const float* __restrict__ bin, float* __restrict__ out)
{
    __shared__ __align__(16) char smem_raw[WPB * DEPTH * ROW * 2];   // 32 KB
    __half (*stage)[DEPTH][ROW] = reinterpret_cast<__half(*)[DEPTH][ROW]>(smem_raw);
    float  (*sred)[ROW]         = reinterpret_cast<float(*)[ROW]>(smem_raw);

    const int b     = blockIdx.x >> 3;
    const int chunk = blockIdx.x & 7;
    const int warp  = threadIdx.x >> 5;
    const int lane  = threadIdx.x & 31;
    const int wc    = chunk * WPB + warp;
    const unsigned FULL = 0xffffffffu;

    // vsum packed: slot A floats [8*lane, +8), slot B +256  (= o*16+d)
    u64 vpA[4], vpB[4];
    {
        const float* vb = g_vsum + (size_t)b * ROW + lane * 8;
        float4 a0 = *reinterpret_cast<const float4*>(vb);
        float4 a1 = *reinterpret_cast<const float4*>(vb + 4);
        float4 b0 = *reinterpret_cast<const float4*>(vb + 256);
        float4 b1 = *reinterpret_cast<const float4*>(vb + 260);
        vpA[0] = pack_f2(a0.x, a0.y); vpA[1] = pack_f2(a0.z, a0.w);
        vpA[2] = pack_f2(a1.x, a1.y); vpA[3] = pack_f2(a1.z, a1.w);
        vpB[0] = pack_f2(b0.x, b0.y); vpB[1] = pack_f2(b0.z, b0.w);
        vpB[2] = pack_f2(b1.x, b1.y); vpB[3] = pack_f2(b1.z, b1.w);
    }

    u64 accA[4], accB[4];
    #pragma unroll
    for (int k = 0; k < 4; ++k) { accA[k] = 0ull; accB[k] = 0ull; }

    const __half* up = g_u16 + ((size_t)b * IC + (size_t)wc * IPW) * ROW;
    const int loff = lane * 8;                 // halves
    const int src0 = lane >> 1;                // shfl source for bin broadcast

    const unsigned sbase =
        (unsigned)__cvta_generic_to_shared(&stage[warp][0][0]) + loff * 2;

    // prologue: rows 0..2 in flight (3 groups)
    #pragma unroll
    for (int p = 0; p < 3; ++p) {
        const __half* g = up + (size_t)p * ROW + loff;
        cp_async16(sbase + p * (ROW * 2), g);
        cp_async16(sbase + p * (ROW * 2) + 512, g + 256);
        asm volatile("cp.async.commit_group;\n" ::: "memory");
    }

    #pragma unroll 4
    for (int ii = 0; ii < IPW; ++ii) {
        const int pf = ii + 3;
        if (pf < IPW) {
            const __half* g = up + (size_t)pf * ROW + loff;
            const unsigned sa = sbase + (pf & (DEPTH - 1)) * (ROW * 2);
            cp_async16(sa, g);
            cp_async16(sa + 512, g + 256);
        }
        asm volatile("cp.async.commit_group;\n" ::: "memory");

        // early LDG of logit prior (L2/L1 resident; lane pairs share addr via shfl)
        const int i = wc * IPW + ii;
        float bv = bin[(size_t)i * OC + lane];

        asm volatile("cp.async.wait_group 3;\n" ::: "memory");   // row ii ready

        const int s = ii & (DEPTH - 1);
        uint4 rA = *reinterpret_cast<const uint4*>(&stage[warp][s][loff]);
        uint4 rB = *reinterpret_cast<const uint4*>(&stage[warp][s][256 + loff]);

        u64 uPA[4], uPB[4];
        {
            const __half2* hA = reinterpret_cast<const __half2*>(&rA);
            const __half2* hB = reinterpret_cast<const __half2*>(&rB);
            #pragma unroll
            for (int k = 0; k < 4; ++k) {
                float2 fa = __half22float2(hA[k]);
                float2 fb = __half22float2(hB[k]);
                uPA[k] = pack_f2(fa.x, fa.y);
                uPB[k] = pack_f2(fb.x, fb.y);
            }
        }

        // packed dot products (FFMA2)
        u64 dA = 0ull, dB = 0ull;
        #pragma unroll
        for (int k = 0; k < 4; ++k) { ffma2(dA, uPA[k], vpA[k]); ffma2(dB, uPB[k], vpB[k]); }
        float al, ah, bl2, bh;
        unpack_f2(dA, al, ah); unpack_f2(dB, bl2, bh);
        float pA = al + ah, pB = bl2 + bh;
        pA += __shfl_xor_sync(FULL, pA, 1);   // full d-dot within lane pair
        pB += __shfl_xor_sync(FULL, pB, 1);

        float blA = __shfl_sync(FULL, bv, src0);
        float blB = __shfl_sync(FULL, bv, 16 + src0);

        float eA = __expf(blA + pA);
        float eB = __expf(blB + pB);
        float Z  = eA + eB;
        // xor{2,4,8,16} sums each of the 32 output caps exactly once
        Z += __shfl_xor_sync(FULL, Z, 2);
        Z += __shfl_xor_sync(FULL, Z, 4);
        Z += __shfl_xor_sync(FULL, Z, 8);
        Z += __shfl_xor_sync(FULL, Z, 16);
        float rZ = __frcp_rn(Z);
        u64 cAp = pack_f2(eA * rZ, eA * rZ);
        u64 cBp = pack_f2(eB * rZ, eB * rZ);

        // packed accumulation (FFMA2)
        #pragma unroll
        for (int k = 0; k < 4; ++k) { ffma2(accA[k], cAp, uPA[k]); ffma2(accB[k], cBp, uPB[k]); }
    }

    asm volatile("cp.async.wait_group 0;\n" ::: "memory");
    __syncthreads();                       // stage dead; safe to alias as sred

    float aa[8], bb[8];
    #pragma unroll
    for (int k = 0; k < 4; ++k) {
        unpack_f2(accA[k], aa[2*k], aa[2*k+1]);
        unpack_f2(accB[k], bb[2*k], bb[2*k+1]);
    }
    float* w0 = &sred[warp][lane * 8];
    *reinterpret_cast<float4*>(w0)       = make_float4(aa[0], aa[1], aa[2], aa[3]);
    *reinterpret_cast<float4*>(w0 + 4)   = make_float4(aa[4], aa[5], aa[6], aa[7]);
    *reinterpret_cast<float4*>(w0 + 256) = make_float4(bb[0], bb[1], bb[2], bb[3]);
    *reinterpret_cast<float4*>(w0 + 260) = make_float4(bb[4], bb[5], bb[6], bb[7]);
    __syncthreads();
    block_tail_reduce(sred, b, chunk, MODE, out);
}

extern "C" void kernel_launch(void* const* d_in, const int* in_sizes, int n_in,
                              void* d_out, int out_size)
{
    const float* u   = (const float*)d_in[0];  // [128,2048,32,16] f32
    const float* bin = (const float*)d_in[1];  // [2048,32] f32
    float* out = (float*)d_out;                // [128,32,16] f32

    const dim3 grid(BATCH * BPB);

    // v0 = squash(sum c0*u), c0 = softmax(bin); emit fp16 u; vsum = v0
    rba_init<<<grid, THREADS>>>(u, bin);
    // iter1: logits = bin + u.v0          ; vsum += v1
    rba_iter<1><<<grid, THREADS>>>(bin, out);
    // iter2: logits = bin + u.(v0+v1)     ; vsum += v2
    rba_iter<1><<<grid, THREADS>>>(bin, out);
    // iter3: logits = bin + u.(v0+v1+v2)  ; out = v3
    rba_iter<2><<<grid, THREADS>>>(bin, out);

    (void)in_sizes; (void)n_in; (void)out_size;
}